// round 10
// baseline (speedup 1.0000x reference)
#include <cuda_runtime.h>
#include <cstdint>

// GRU via warp-level HMMA (mma.sync m16n8k16 bf16->fp32).
// 128 CTAs x 256 threads; CTA owns 8 batch rows for all 784 steps.
// Gate-colocated M-tiles: warp w computes r/z/n gates of hidden units
// [16w,16w+16) -> gate math fully in registers, 1 barrier/step.
// Precision: Wh = W_hi + W_lo, h = h_hi + h_lo (bf16 splits), 3-pass fp32 acc.
// W_hi register-resident; W_lo SMEM fragment-interleaved (1 LDS.128 each).
// h tiles stored in HMMA-fragment word order -> 1 LDS.64 per operand tile.
// Gates use MUFU.TANH (tanh.approx.f32): 12 MUFU/thread/step vs 24.

#define HID   128
#define SEQ   784
#define ROWS  8
#define NT    256
#define NCTA  128

#define B_STRIDE  272                    // bytes per n row (256 + 16 pad)
#define XS_STRIDE 788                    // floats per x row (784 + 4 pad)

#define OFF_WLO 0                        // 24*8*32*16 = 98304 B
#define OFF_XS  98304                    // 8*788*4 = 25216 B
#define OFF_BH  123520                   // 2 bufs x 2176
#define OFF_BL  127872                   // 2 bufs x 2176
#define SMEM_BYTES (127872 + 4352)       // 132224 B

__device__ __forceinline__ uint16_t f2bf(float f) {
    uint16_t h;
    asm("cvt.rn.bf16.f32 %0, %1;" : "=h"(h) : "f"(f));
    return h;
}
__device__ __forceinline__ float bf2f(uint16_t h) {
    return __uint_as_float((uint32_t)h << 16);
}
__device__ __forceinline__ uint32_t pack_hi(float w0, float w1) {
    return (uint32_t)f2bf(w0) | ((uint32_t)f2bf(w1) << 16);
}
__device__ __forceinline__ uint32_t pack_lo(float w0, float w1) {
    float r0 = w0 - bf2f(f2bf(w0));
    float r1 = w1 - bf2f(f2bf(w1));
    return (uint32_t)f2bf(r0) | ((uint32_t)f2bf(r1) << 16);
}
__device__ __forceinline__ void mma16816(float* c, const uint32_t* a,
                                         uint32_t b0, uint32_t b1) {
    asm volatile(
        "mma.sync.aligned.m16n8k16.row.col.f32.bf16.bf16.f32 "
        "{%0,%1,%2,%3}, {%4,%5,%6,%7}, {%8,%9}, {%0,%1,%2,%3};"
        : "+f"(c[0]), "+f"(c[1]), "+f"(c[2]), "+f"(c[3])
        : "r"(a[0]), "r"(a[1]), "r"(a[2]), "r"(a[3]), "r"(b0), "r"(b1));
}
__device__ __forceinline__ float mufu_tanh(float x) {
    float r;
    asm("tanh.approx.f32 %0, %1;" : "=f"(r) : "f"(x));
    return r;
}

extern __shared__ __align__(16) char smem[];

__global__ __launch_bounds__(NT, 1)
void gru_hmma3_kernel(const float* __restrict__ x,
                      const float* __restrict__ Wi,
                      const float* __restrict__ bi,
                      const float* __restrict__ Wh,
                      const float* __restrict__ bh,
                      const float* __restrict__ Wfc,
                      const float* __restrict__ bfc,
                      float* __restrict__ out) {
    const int tid  = threadIdx.x;
    const int lane = tid & 31;
    const int wid  = tid >> 5;
    const int row0 = blockIdx.x * ROWS;

    // ownership after MMA: units (i0, i0+8), batch cols (n0, n0+1)
    const int i0 = 16 * wid + (lane >> 2);
    const int n0 = 2 * (lane & 3);

    // ---- prologue: W_hi -> regs, W_lo -> SMEM (gate-colocated tiles) ----
    uint32_t af[3][8][4];
#pragma unroll
    for (int j = 0; j < 3; ++j) {            // 0=r,1=z,2=n
#pragma unroll
        for (int kt = 0; kt < 8; ++kt) {
            uint32_t lo[4];
#pragma unroll
            for (int r = 0; r < 4; ++r) {
                const int g = j * HID + 16 * wid + (lane >> 2) + ((r & 1) ? 8 : 0);
                const int k = kt * 16 + (lane & 3) * 2 + ((r & 2) ? 8 : 0);
                const float w0 = Wh[g * HID + k];
                const float w1 = Wh[g * HID + k + 1];
                af[j][kt][r] = pack_hi(w0, w1);
                lo[r]        = pack_lo(w0, w1);
            }
            *(uint4*)(smem + OFF_WLO + (((wid * 3 + j) * 8 + kt) * 32 + lane) * 16) =
                make_uint4(lo[0], lo[1], lo[2], lo[3]);
        }
    }
    // x slice -> SMEM
    {
        float* xs = (float*)(smem + OFF_XS);
        for (int idx = tid; idx < ROWS * SEQ; idx += NT) {
            const int r = idx / SEQ;
            const int t = idx - r * SEQ;
            xs[r * XS_STRIDE + t] = x[(long)(row0 + r) * SEQ + t];
        }
    }
    // zero h hi/lo tiles (both buffers)
    for (int idx = tid; idx < 2176; idx += NT)
        ((uint32_t*)(smem + OFF_BH))[idx] = 0u;

    // gate constants (r/z halved for sigmoid-via-tanh folding)
    const float wi0a = 0.5f * Wi[i0],         wi0b = 0.5f * Wi[i0 + 8];
    const float wi1a = 0.5f * Wi[i0 + HID],   wi1b = 0.5f * Wi[i0 + 8 + HID];
    const float wi2a = Wi[i0 + 2*HID],        wi2b = Wi[i0 + 8 + 2*HID];
    const float bra  = 0.5f * (bi[i0] + bh[i0]);
    const float brb  = 0.5f * (bi[i0+8] + bh[i0+8]);
    const float bza  = 0.5f * (bi[i0+HID] + bh[i0+HID]);
    const float bzb  = 0.5f * (bi[i0+8+HID] + bh[i0+8+HID]);
    const float bnia = bi[i0+2*HID],          bnib = bi[i0+8+2*HID];
    const float bnha = bh[i0+2*HID],          bnhb = bh[i0+8+2*HID];

    float hprev[4];                      // (i0,n0),(i0,n1),(i1,n0),(i1,n1)
#pragma unroll
    for (int q = 0; q < 4; ++q) hprev[q] = 0.0f;

    const float* xs0 = (const float*)(smem + OFF_XS) + n0 * XS_STRIDE;
    const float* xs1 = xs0 + XS_STRIDE;

    // fragment-layout addressing
    // read: this thread's B pair (w=lane&3, w+4) is 8B-contiguous
    const char* pbrd = smem + (lane >> 2) * B_STRIDE + (lane & 3) * 8;
    // write: unit i0 -> byte fb, unit i0+8 -> fb+4 (within its n row)
    const int fb = wid * 32 + (((lane >> 2) >> 1) << 3) + ((lane >> 2) & 1) * 2;
    const char* wlo_base = smem + OFF_WLO + (wid * 3 * 8 * 32 + lane) * 16;

    __syncthreads();

#pragma unroll 1
    for (int t = 0; t < SEQ; ++t) {
        const int rsel = (t & 1) * 2176;
        const int wsel = ((t + 1) & 1) * 2176;

        float C[3][4];
#pragma unroll
        for (int j = 0; j < 3; ++j)
#pragma unroll
            for (int q = 0; q < 4; ++q) C[j][q] = 0.0f;

        const float xv0 = xs0[t];
        const float xv1 = xs1[t];

#pragma unroll
        for (int kt = 0; kt < 8; ++kt) {
            const uint2 hh = *(const uint2*)(pbrd + OFF_BH + rsel + kt * 32);
            const uint2 ll = *(const uint2*)(pbrd + OFF_BL + rsel + kt * 32);
#pragma unroll
            for (int j = 0; j < 3; ++j) {
                const uint4 wl = *(const uint4*)(wlo_base + (j * 8 + kt) * 512);
                mma16816(C[j], af[j][kt], hh.x, hh.y);        // W_hi * h_hi
                mma16816(C[j], af[j][kt], ll.x, ll.y);        // W_hi * h_lo
                const uint32_t wla[4] = {wl.x, wl.y, wl.z, wl.w};
                mma16816(C[j], wla, hh.x, hh.y);              // W_lo * h_hi
            }
        }

        // ---- gate math in registers (MUFU.TANH); store h hi/lo ----
        char* bhp = smem + OFF_BH + wsel;
        char* blp = smem + OFF_BL + wsel;
#pragma unroll
        for (int q = 0; q < 4; ++q) {
            const bool second = (q >= 2);
            const float xv  = (q & 1) ? xv1 : xv0;
            const int   n   = (q & 1) ? (n0 + 1) : n0;
            const float wiA = second ? wi0b : wi0a;
            const float wiB = second ? wi1b : wi1a;
            const float wiC = second ? wi2b : wi2a;
            const float bR  = second ? brb  : bra;
            const float bZ  = second ? bzb  : bza;
            const float bNi = second ? bnib : bnia;
            const float bNh = second ? bnhb : bnha;

            // r = sigmoid(C0 + xv*wi + b) = 0.5*tanh(0.5*(...)) + 0.5
            const float rr = fmaf(0.5f,
                mufu_tanh(fmaf(0.5f, C[0][q], fmaf(xv, wiA, bR))), 0.5f);
            const float zz = fmaf(0.5f,
                mufu_tanh(fmaf(0.5f, C[1][q], fmaf(xv, wiB, bZ))), 0.5f);
            const float nn =
                mufu_tanh(fmaf(xv, wiC, bNi) + rr * (C[2][q] + bNh));
            const float h = nn + zz * (hprev[q] - nn);
            hprev[q] = h;

            const uint16_t hb = f2bf(h);
            const uint16_t lb = f2bf(h - bf2f(hb));
            const int off = n * B_STRIDE + fb + (second ? 4 : 0);
            *(uint16_t*)(bhp + off) = hb;
            *(uint16_t*)(blp + off) = lb;
        }
        __syncthreads();
    }

    // ---- final FC: logits = h @ Wfc^T + bfc ----
    float* hf = (float*)(smem + OFF_XS);   // reuse: hf[i][n]
    {
        hf[i0 * ROWS + n0]           = hprev[0];
        hf[i0 * ROWS + n0 + 1]       = hprev[1];
        hf[(i0 + 8) * ROWS + n0]     = hprev[2];
        hf[(i0 + 8) * ROWS + n0 + 1] = hprev[3];
    }
    __syncthreads();

    if (tid < ROWS * 10) {
        const int r = tid / 10;
        const int o = tid - r * 10;
        float s = bfc[o];
        const float* wf = Wfc + o * HID;
#pragma unroll 8
        for (int k = 0; k < HID; ++k) s = fmaf(hf[k * ROWS + r], wf[k], s);
        out[(long)(row0 + r) * 10 + o] = s;
    }
}

extern "C" void kernel_launch(void* const* d_in, const int* in_sizes, int n_in,
                              void* d_out, int out_size) {
    const float* x   = (const float*)d_in[0];
    const float* Wi  = (const float*)d_in[1];
    const float* bi  = (const float*)d_in[2];
    const float* Wh  = (const float*)d_in[3];
    const float* bh  = (const float*)d_in[4];
    const float* Wfc = (const float*)d_in[5];
    const float* bfc = (const float*)d_in[6];
    float* out = (float*)d_out;

    cudaFuncSetAttribute(gru_hmma3_kernel,
                         cudaFuncAttributeMaxDynamicSharedMemorySize, SMEM_BYTES);
    gru_hmma3_kernel<<<NCTA, NT, SMEM_BYTES>>>(x, Wi, bi, Wh, bh, Wfc, bfc, out);
}

// round 11
// speedup vs baseline: 1.4717x; 1.4717x over previous
#include <cuda_runtime.h>
#include <cstdint>

// GRU via warp-level HMMA (mma.sync m16n8k16 f16->fp32), 2-pass f16 split.
// 128 CTAs x 256 threads; CTA owns 8 batch rows for all 784 steps.
// Gate-colocated M-tiles: warp w computes r/z/n gates of hidden units
// [16w,16w+16) -> gate math fully in registers, 1 barrier/step.
// Precision: W rounded to f16 once (|dW/W| <= 2^-12, fixed perturbation);
// h = h_hi + h_lo (f16 pair, error 2^-22). gh = W*(h_hi) + W*(h_lo), fp32 acc.
// 48 HMMA/warp/step (vs 72 in 3-pass bf16), no W_lo SMEM stream.
// MMA order j-outer (r,z,n) with B in regs so rr/zz MUFU math overlaps the
// n-gate MMA stream.

#define HID   128
#define SEQ   784
#define ROWS  8
#define NT    256
#define NCTA  128

#define B_STRIDE  272                    // bytes per n row (256 + 16 pad)
#define XS_STRIDE 788                    // floats per x row (784 + 4 pad)

#define OFF_XS  0                        // 8*788*4 = 25216 B
#define OFF_BH  25216                    // 2 bufs x 2176
#define OFF_BL  29568                    // 2 bufs x 2176
#define SMEM_BYTES (29568 + 4352)        // 33920 B

__device__ __forceinline__ uint16_t f2h(float f) {
    uint16_t h;
    asm("cvt.rn.f16.f32 %0, %1;" : "=h"(h) : "f"(f));
    return h;
}
__device__ __forceinline__ float h2f(uint16_t h) {
    float f;
    asm("cvt.f32.f16 %0, %1;" : "=f"(f) : "h"(h));
    return f;
}
__device__ __forceinline__ uint32_t pack_h16(float w0, float w1) {
    return (uint32_t)f2h(w0) | ((uint32_t)f2h(w1) << 16);
}
__device__ __forceinline__ void mma16816(float* c, const uint32_t* a,
                                         uint32_t b0, uint32_t b1) {
    asm volatile(
        "mma.sync.aligned.m16n8k16.row.col.f32.f16.f16.f32 "
        "{%0,%1,%2,%3}, {%4,%5,%6,%7}, {%8,%9}, {%0,%1,%2,%3};"
        : "+f"(c[0]), "+f"(c[1]), "+f"(c[2]), "+f"(c[3])
        : "r"(a[0]), "r"(a[1]), "r"(a[2]), "r"(a[3]), "r"(b0), "r"(b1));
}
__device__ __forceinline__ float mufu_tanh(float x) {
    float r;
    asm("tanh.approx.f32 %0, %1;" : "=f"(r) : "f"(x));
    return r;
}

extern __shared__ __align__(16) char smem[];

__global__ __launch_bounds__(NT, 1)
void gru_hmma4_kernel(const float* __restrict__ x,
                      const float* __restrict__ Wi,
                      const float* __restrict__ bi,
                      const float* __restrict__ Wh,
                      const float* __restrict__ bh,
                      const float* __restrict__ Wfc,
                      const float* __restrict__ bfc,
                      float* __restrict__ out) {
    const int tid  = threadIdx.x;
    const int lane = tid & 31;
    const int wid  = tid >> 5;
    const int row0 = blockIdx.x * ROWS;

    // ownership after MMA: units (i0, i0+8), batch cols (n0, n0+1)
    const int i0 = 16 * wid + (lane >> 2);
    const int n0 = 2 * (lane & 3);

    // ---- prologue: W (f16) -> register A-fragments, gate-colocated ----
    uint32_t af[3][8][4];
#pragma unroll
    for (int j = 0; j < 3; ++j) {            // 0=r,1=z,2=n
#pragma unroll
        for (int kt = 0; kt < 8; ++kt) {
#pragma unroll
            for (int r = 0; r < 4; ++r) {
                const int g = j * HID + 16 * wid + (lane >> 2) + ((r & 1) ? 8 : 0);
                const int k = kt * 16 + (lane & 3) * 2 + ((r & 2) ? 8 : 0);
                af[j][kt][r] = pack_h16(Wh[g * HID + k], Wh[g * HID + k + 1]);
            }
        }
    }
    // x slice -> SMEM
    {
        float* xs = (float*)(smem + OFF_XS);
        for (int idx = tid; idx < ROWS * SEQ; idx += NT) {
            const int r = idx / SEQ;
            const int t = idx - r * SEQ;
            xs[r * XS_STRIDE + t] = x[(long)(row0 + r) * SEQ + t];
        }
    }
    // zero h hi/lo tiles (both buffers)
    for (int idx = tid; idx < 2176; idx += NT)
        ((uint32_t*)(smem + OFF_BH))[idx] = 0u;

    // gate constants (r/z halved for sigmoid-via-tanh folding)
    const float wi0a = 0.5f * Wi[i0],         wi0b = 0.5f * Wi[i0 + 8];
    const float wi1a = 0.5f * Wi[i0 + HID],   wi1b = 0.5f * Wi[i0 + 8 + HID];
    const float wi2a = Wi[i0 + 2*HID],        wi2b = Wi[i0 + 8 + 2*HID];
    const float bra  = 0.5f * (bi[i0] + bh[i0]);
    const float brb  = 0.5f * (bi[i0+8] + bh[i0+8]);
    const float bza  = 0.5f * (bi[i0+HID] + bh[i0+HID]);
    const float bzb  = 0.5f * (bi[i0+8+HID] + bh[i0+8+HID]);
    const float bnia = bi[i0+2*HID],          bnib = bi[i0+8+2*HID];
    const float bnha = bh[i0+2*HID],          bnhb = bh[i0+8+2*HID];

    float hprev[4];                      // (i0,n0),(i0,n1),(i1,n0),(i1,n1)
#pragma unroll
    for (int q = 0; q < 4; ++q) hprev[q] = 0.0f;

    const float* xs0 = (const float*)(smem + OFF_XS) + n0 * XS_STRIDE;
    const float* xs1 = xs0 + XS_STRIDE;

    // fragment-layout addressing (identical 2B-element layout as bf16 version)
    const char* pbrd = smem + (lane >> 2) * B_STRIDE + (lane & 3) * 8;
    const int fb = wid * 32 + (((lane >> 2) >> 1) << 3) + ((lane >> 2) & 1) * 2;

    __syncthreads();

#pragma unroll 1
    for (int t = 0; t < SEQ; ++t) {
        const int rsel = (t & 1) * 2176;
        const int wsel = ((t + 1) & 1) * 2176;

        const float xv0 = xs0[t];
        const float xv1 = xs1[t];

        // ---- load all B fragments for this step into registers ----
        uint32_t Bh[8][2], Bl[8][2];
#pragma unroll
        for (int kt = 0; kt < 8; ++kt) {
            const uint2 hh = *(const uint2*)(pbrd + OFF_BH + rsel + kt * 32);
            const uint2 ll = *(const uint2*)(pbrd + OFF_BL + rsel + kt * 32);
            Bh[kt][0] = hh.x; Bh[kt][1] = hh.y;
            Bl[kt][0] = ll.x; Bl[kt][1] = ll.y;
        }

        float C[3][4];
#pragma unroll
        for (int j = 0; j < 3; ++j)
#pragma unroll
            for (int q = 0; q < 4; ++q) C[j][q] = 0.0f;

        // ---- r-gate and z-gate MMA streams ----
#pragma unroll
        for (int kt = 0; kt < 8; ++kt) {
            mma16816(C[0], af[0][kt], Bh[kt][0], Bh[kt][1]);
            mma16816(C[0], af[0][kt], Bl[kt][0], Bl[kt][1]);
        }
#pragma unroll
        for (int kt = 0; kt < 8; ++kt) {
            mma16816(C[1], af[1][kt], Bh[kt][0], Bh[kt][1]);
            mma16816(C[1], af[1][kt], Bl[kt][0], Bl[kt][1]);
        }

        // ---- rr/zz gate math (MUFU) — overlaps the n-gate MMA stream below
        float rr[4], zz[4];
#pragma unroll
        for (int q = 0; q < 4; ++q) {
            const bool second = (q >= 2);
            const float xv  = (q & 1) ? xv1 : xv0;
            const float wiA = second ? wi0b : wi0a;
            const float wiB = second ? wi1b : wi1a;
            const float bR  = second ? brb  : bra;
            const float bZ  = second ? bzb  : bza;
            rr[q] = fmaf(0.5f,
                mufu_tanh(fmaf(0.5f, C[0][q], fmaf(xv, wiA, bR))), 0.5f);
            zz[q] = fmaf(0.5f,
                mufu_tanh(fmaf(0.5f, C[1][q], fmaf(xv, wiB, bZ))), 0.5f);
        }

        // ---- n-gate MMA stream ----
#pragma unroll
        for (int kt = 0; kt < 8; ++kt) {
            mma16816(C[2], af[2][kt], Bh[kt][0], Bh[kt][1]);
            mma16816(C[2], af[2][kt], Bl[kt][0], Bl[kt][1]);
        }

        // ---- n-gate + h update; store h hi/lo for next step ----
        char* bhp = smem + OFF_BH + wsel;
        char* blp = smem + OFF_BL + wsel;
#pragma unroll
        for (int q = 0; q < 4; ++q) {
            const bool second = (q >= 2);
            const float xv  = (q & 1) ? xv1 : xv0;
            const int   n   = (q & 1) ? (n0 + 1) : n0;
            const float wiC = second ? wi2b : wi2a;
            const float bNi = second ? bnib : bnia;
            const float bNh = second ? bnhb : bnha;

            const float nn =
                mufu_tanh(fmaf(xv, wiC, bNi) + rr[q] * (C[2][q] + bNh));
            const float h = nn + zz[q] * (hprev[q] - nn);
            hprev[q] = h;

            const uint16_t hb = f2h(h);
            const uint16_t lb = f2h(h - h2f(hb));
            const int off = n * B_STRIDE + fb + (second ? 4 : 0);
            *(uint16_t*)(bhp + off) = hb;
            *(uint16_t*)(blp + off) = lb;
        }
        __syncthreads();
    }

    // ---- final FC: logits = h @ Wfc^T + bfc ----
    float* hf = (float*)(smem + OFF_XS);   // reuse: hf[i][n]
    {
        hf[i0 * ROWS + n0]           = hprev[0];
        hf[i0 * ROWS + n0 + 1]       = hprev[1];
        hf[(i0 + 8) * ROWS + n0]     = hprev[2];
        hf[(i0 + 8) * ROWS + n0 + 1] = hprev[3];
    }
    __syncthreads();

    if (tid < ROWS * 10) {
        const int r = tid / 10;
        const int o = tid - r * 10;
        float s = bfc[o];
        const float* wf = Wfc + o * HID;
#pragma unroll 8
        for (int k = 0; k < HID; ++k) s = fmaf(hf[k * ROWS + r], wf[k], s);
        out[(long)(row0 + r) * 10 + o] = s;
    }
}

extern "C" void kernel_launch(void* const* d_in, const int* in_sizes, int n_in,
                              void* d_out, int out_size) {
    const float* x   = (const float*)d_in[0];
    const float* Wi  = (const float*)d_in[1];
    const float* bi  = (const float*)d_in[2];
    const float* Wh  = (const float*)d_in[3];
    const float* bh  = (const float*)d_in[4];
    const float* Wfc = (const float*)d_in[5];
    const float* bfc = (const float*)d_in[6];
    float* out = (float*)d_out;

    cudaFuncSetAttribute(gru_hmma4_kernel,
                         cudaFuncAttributeMaxDynamicSharedMemorySize, SMEM_BYTES);
    gru_hmma4_kernel<<<NCTA, NT, SMEM_BYTES>>>(x, Wi, bi, Wh, bh, Wfc, bfc, out);
}